// round 2
// baseline (speedup 1.0000x reference)
#include <cuda_runtime.h>
#include <math.h>

#define NMAX 100000
#define DD 64
#define HH 32

// -------- persistent scratch (device globals; no allocation allowed) --------
__device__ __align__(16) float g_ap[NMAX * DD];
__device__ __align__(16) float g_an[NMAX * DD];
__device__ __align__(16) float g_cntp[NMAX];
__device__ __align__(16) float g_cntn[NMAX];
__device__ __align__(16) float g_xp[NMAX * HH];
__device__ __align__(16) float g_xn[NMAX * HH];
__device__ __align__(16) float g_A[NMAX * HH];  // mean_agg(xp, pos)
__device__ __align__(16) float g_B[NMAX * HH];  // mean_agg(xn, neg)
__device__ __align__(16) float g_C[NMAX * HH];  // mean_agg(xn, pos)
__device__ __align__(16) float g_D[NMAX * HH];  // mean_agg(xp, neg)

__device__ __forceinline__ void red_v4(float* p, float4 v) {
    asm volatile("red.global.add.v4.f32 [%0], {%1,%2,%3,%4};"
                 :: "l"(p), "f"(v.x), "f"(v.y), "f"(v.z), "f"(v.w)
                 : "memory");
}

// -------------------------------- zeroing ----------------------------------
__global__ void k_zero(int n) {
    size_t i = (size_t)blockIdx.x * blockDim.x + threadIdx.x;
    size_t stride = (size_t)gridDim.x * blockDim.x;
    float4 z4 = make_float4(0.f, 0.f, 0.f, 0.f);
    size_t nd = (size_t)n * DD / 4;
    for (size_t j = i; j < nd; j += stride) {
        ((float4*)g_ap)[j] = z4;
        ((float4*)g_an)[j] = z4;
    }
    size_t nh = (size_t)n * HH / 4;
    for (size_t j = i; j < nh; j += stride) {
        ((float4*)g_A)[j] = z4;
        ((float4*)g_B)[j] = z4;
        ((float4*)g_C)[j] = z4;
        ((float4*)g_D)[j] = z4;
    }
    size_t nc = (size_t)n / 4;
    for (size_t j = i; j < nc; j += stride) {
        ((float4*)g_cntp)[j] = z4;
        ((float4*)g_cntn)[j] = z4;
    }
}

// --------------------------- layer-1 aggregation ----------------------------
// one thread per (edge, 16B chunk); 16 threads cover one edge's 64 floats.
__global__ void k_edge1(const float* __restrict__ x, const int* __restrict__ ei,
                        long total) {
    long idx = (long)blockIdx.x * blockDim.x + threadIdx.x;
    if (idx >= total) return;
    int e = (int)(idx >> 4);
    int c = (int)(idx & 15);
    long eb = 3L * e;
    int s  = __ldg(ei + eb);
    int d  = __ldg(ei + eb + 1);
    int sg = __ldg(ei + eb + 2);
    float4 v = *(const float4*)(x + (size_t)s * DD + c * 4);
    float* buf = (sg > 0) ? g_ap : g_an;
    red_v4(buf + (size_t)d * DD + c * 4, v);
    if (c == 0) atomicAdd((sg > 0) ? (g_cntp + d) : (g_cntn + d), 1.0f);
}

// --------------------------- layer-2 aggregation ----------------------------
// chunks 0..7 gather xp[src], 8..15 gather xn[src].
// pos: xp->A, xn->C ; neg: xp->D, xn->B
__global__ void k_edge2(const int* __restrict__ ei, long total) {
    long idx = (long)blockIdx.x * blockDim.x + threadIdx.x;
    if (idx >= total) return;
    int e = (int)(idx >> 4);
    int c = (int)(idx & 15);
    long eb = 3L * e;
    int s  = __ldg(ei + eb);
    int d  = __ldg(ei + eb + 1);
    int sg = __ldg(ei + eb + 2);
    int cc = c & 7;
    bool first = (c < 8);
    const float* srcb = first ? g_xp : g_xn;
    float4 v = *(const float4*)(srcb + (size_t)s * HH + cc * 4);
    float* dstb;
    if (sg > 0) dstb = first ? g_A : g_C;
    else        dstb = first ? g_D : g_B;
    red_v4(dstb + (size_t)d * HH + cc * 4, v);
}

// ------------------------------- node layer 1 -------------------------------
// warp per node: hp=[ap/cnt, x]@Wp1+bp1, hn=[an/cnt, x]@Wn1+bn1, xp/xn = tanh
__global__ void k_node1(const float* __restrict__ x,
                        const float* __restrict__ Wp1, const float* __restrict__ bp1,
                        const float* __restrict__ Wn1, const float* __restrict__ bn1,
                        int n_nodes) {
    __shared__ float Wp[128 * 32], Wn[128 * 32], bp[32], bn[32];
    int tid = threadIdx.x;
    for (int i = tid; i < 128 * 32; i += blockDim.x) {
        Wp[i] = Wp1[i];
        Wn[i] = Wn1[i];
    }
    if (tid < 32) { bp[tid] = bp1[tid]; bn[tid] = bn1[tid]; }
    __syncthreads();

    int lane = tid & 31, w = tid >> 5;
    for (int n = blockIdx.x * 8 + w; n < n_nodes; n += gridDim.x * 8) {
        float invp = 1.0f / fmaxf(g_cntp[n], 1.0f);
        float invn = 1.0f / fmaxf(g_cntn[n], 1.0f);
        size_t nb = (size_t)n * 64;
        float ap0 = g_ap[nb + lane] * invp;
        float ap1 = g_ap[nb + 32 + lane] * invp;
        float an0 = g_an[nb + lane] * invn;
        float an1 = g_an[nb + 32 + lane] * invn;
        float x0  = x[nb + lane];
        float x1  = x[nb + 32 + lane];
        float accp = bp[lane], accn = bn[lane];
#pragma unroll
        for (int k = 0; k < 32; k++) {
            float a0 = __shfl_sync(0xffffffffu, ap0, k);
            float a1 = __shfl_sync(0xffffffffu, ap1, k);
            float b0 = __shfl_sync(0xffffffffu, an0, k);
            float b1 = __shfl_sync(0xffffffffu, an1, k);
            float u0 = __shfl_sync(0xffffffffu, x0, k);
            float u1 = __shfl_sync(0xffffffffu, x1, k);
            accp += a0 * Wp[k * 32 + lane] + a1 * Wp[(32 + k) * 32 + lane]
                  + u0 * Wp[(64 + k) * 32 + lane] + u1 * Wp[(96 + k) * 32 + lane];
            accn += b0 * Wn[k * 32 + lane] + b1 * Wn[(32 + k) * 32 + lane]
                  + u0 * Wn[(64 + k) * 32 + lane] + u1 * Wn[(96 + k) * 32 + lane];
        }
        g_xp[(size_t)n * 32 + lane] = tanhf(accp);
        g_xn[(size_t)n * 32 + lane] = tanhf(accn);
    }
}

// ------------------------------- node layer 2 -------------------------------
// hp2=[A/cp,B/cn,xp]@Wp2+bp2 ; hn2=[C/cp,D/cn,xn]@Wn2+bn2 ; z=tanh(tanh(.)@Ww+bw)
__global__ void k_node2a(const float* __restrict__ Wp2, const float* __restrict__ bp2,
                         const float* __restrict__ Wn2, const float* __restrict__ bn2,
                         const float* __restrict__ Ww,  const float* __restrict__ bw,
                         float* __restrict__ outz, int n_nodes) {
    __shared__ float Wp[96 * 32], Wn[96 * 32], W3[64 * 64];
    __shared__ float bp[32], bn[32], bwv[64];
    int tid = threadIdx.x;
    for (int i = tid; i < 96 * 32; i += blockDim.x) { Wp[i] = Wp2[i]; Wn[i] = Wn2[i]; }
    for (int i = tid; i < 64 * 64; i += blockDim.x) W3[i] = Ww[i];
    if (tid < 32) { bp[tid] = bp2[tid]; bn[tid] = bn2[tid]; }
    if (tid < 64) bwv[tid] = bw[tid];
    __syncthreads();

    int lane = tid & 31, w = tid >> 5;
    for (int n = blockIdx.x * 8 + w; n < n_nodes; n += gridDim.x * 8) {
        float invp = 1.0f / fmaxf(g_cntp[n], 1.0f);
        float invn = 1.0f / fmaxf(g_cntn[n], 1.0f);
        size_t nb = (size_t)n * 32;
        float Av = g_A[nb + lane] * invp;
        float Bv = g_B[nb + lane] * invn;
        float Cv = g_C[nb + lane] * invp;
        float Dv = g_D[nb + lane] * invn;
        float Xp = g_xp[nb + lane];
        float Xn = g_xn[nb + lane];
        float accp = bp[lane], accn = bn[lane];
#pragma unroll
        for (int k = 0; k < 32; k++) {
            float av = __shfl_sync(0xffffffffu, Av, k);
            float bv = __shfl_sync(0xffffffffu, Bv, k);
            float pv = __shfl_sync(0xffffffffu, Xp, k);
            float cv = __shfl_sync(0xffffffffu, Cv, k);
            float dv = __shfl_sync(0xffffffffu, Dv, k);
            float nv = __shfl_sync(0xffffffffu, Xn, k);
            accp += av * Wp[k * 32 + lane] + bv * Wp[(32 + k) * 32 + lane]
                  + pv * Wp[(64 + k) * 32 + lane];
            accn += cv * Wn[k * 32 + lane] + dv * Wn[(32 + k) * 32 + lane]
                  + nv * Wn[(64 + k) * 32 + lane];
        }
        float zl = tanhf(accp), zh = tanhf(accn);
        float acc0 = bwv[lane], acc1 = bwv[32 + lane];
#pragma unroll
        for (int k = 0; k < 32; k++) {
            float u = __shfl_sync(0xffffffffu, zl, k);
            float v = __shfl_sync(0xffffffffu, zh, k);
            acc0 += u * W3[k * 64 + lane]      + v * W3[(32 + k) * 64 + lane];
            acc1 += u * W3[k * 64 + 32 + lane] + v * W3[(32 + k) * 64 + 32 + lane];
        }
        size_t ob = (size_t)n * 64;
        outz[ob + lane]      = tanhf(acc0);
        outz[ob + 32 + lane] = tanhf(acc1);
    }
}

// ------------------------------- MLP head -----------------------------------
__global__ void k_node2b(const float* __restrict__ Wm1, const float* __restrict__ bm1,
                         const float* __restrict__ g1,  const float* __restrict__ be1,
                         const float* __restrict__ rm1, const float* __restrict__ rv1,
                         const float* __restrict__ Wm2, const float* __restrict__ bm2,
                         const float* __restrict__ g2,  const float* __restrict__ be2,
                         const float* __restrict__ rm2, const float* __restrict__ rv2,
                         const float* __restrict__ Wm3, const float* __restrict__ bm3,
                         const float* __restrict__ outz, float* __restrict__ outp,
                         int n_nodes) {
    __shared__ float W1[64 * 64], W2[64 * 64], w3[64];
    __shared__ float sc1[64], of1[64], sc2[64], of2[64];
    __shared__ float b3;
    int tid = threadIdx.x;
    for (int i = tid; i < 64 * 64; i += blockDim.x) { W1[i] = Wm1[i]; W2[i] = Wm2[i]; }
    if (tid < 64) {
        float s1 = g1[tid] * rsqrtf(rv1[tid] + 1e-5f);
        sc1[tid] = s1;
        of1[tid] = (bm1[tid] - rm1[tid]) * s1 + be1[tid];
        float s2 = g2[tid] * rsqrtf(rv2[tid] + 1e-5f);
        sc2[tid] = s2;
        of2[tid] = (bm2[tid] - rm2[tid]) * s2 + be2[tid];
        w3[tid] = Wm3[tid];
    }
    if (tid == 0) b3 = bm3[0];
    __syncthreads();

    int lane = tid & 31, w = tid >> 5;
    for (int n = blockIdx.x * 8 + w; n < n_nodes; n += gridDim.x * 8) {
        size_t ob = (size_t)n * 64;
        float z0 = outz[ob + lane];
        float z1 = outz[ob + 32 + lane];
        float t0 = 0.f, t1 = 0.f;
#pragma unroll
        for (int k = 0; k < 32; k++) {
            float u = __shfl_sync(0xffffffffu, z0, k);
            float v = __shfl_sync(0xffffffffu, z1, k);
            t0 += u * W1[k * 64 + lane]      + v * W1[(32 + k) * 64 + lane];
            t1 += u * W1[k * 64 + 32 + lane] + v * W1[(32 + k) * 64 + 32 + lane];
        }
        float h0 = fmaxf(t0 * sc1[lane] + of1[lane], 0.f);
        float h1 = fmaxf(t1 * sc1[32 + lane] + of1[32 + lane], 0.f);
        float q0 = 0.f, q1 = 0.f;
#pragma unroll
        for (int k = 0; k < 32; k++) {
            float u = __shfl_sync(0xffffffffu, h0, k);
            float v = __shfl_sync(0xffffffffu, h1, k);
            q0 += u * W2[k * 64 + lane]      + v * W2[(32 + k) * 64 + lane];
            q1 += u * W2[k * 64 + 32 + lane] + v * W2[(32 + k) * 64 + 32 + lane];
        }
        float r0 = fmaxf(q0 * sc2[lane] + of2[lane], 0.f);
        float r1 = fmaxf(q1 * sc2[32 + lane] + of2[32 + lane], 0.f);
        float part = r0 * w3[lane] + r1 * w3[32 + lane];
#pragma unroll
        for (int o = 16; o; o >>= 1)
            part += __shfl_down_sync(0xffffffffu, part, o);
        if (lane == 0)
            outp[n] = 1.0f / (1.0f + expf(-(part + b3)));
    }
}

// -------------------------------- launcher ----------------------------------
extern "C" void kernel_launch(void* const* d_in, const int* in_sizes, int n_in,
                              void* d_out, int out_size) {
    const float* x   = (const float*)d_in[0];
    const int*   ei  = (const int*)d_in[1];
    const float* Wp1 = (const float*)d_in[2];
    const float* bp1 = (const float*)d_in[3];
    const float* Wn1 = (const float*)d_in[4];
    const float* bn1 = (const float*)d_in[5];
    const float* Wp2 = (const float*)d_in[6];
    const float* bp2 = (const float*)d_in[7];
    const float* Wn2 = (const float*)d_in[8];
    const float* bn2 = (const float*)d_in[9];
    const float* Ww  = (const float*)d_in[10];
    const float* bw  = (const float*)d_in[11];
    const float* Wm1 = (const float*)d_in[12];
    const float* bm1 = (const float*)d_in[13];
    const float* g1  = (const float*)d_in[14];
    const float* be1 = (const float*)d_in[15];
    const float* rm1 = (const float*)d_in[16];
    const float* rv1 = (const float*)d_in[17];
    const float* Wm2 = (const float*)d_in[18];
    const float* bm2 = (const float*)d_in[19];
    const float* g2  = (const float*)d_in[20];
    const float* be2 = (const float*)d_in[21];
    const float* rm2 = (const float*)d_in[22];
    const float* rv2 = (const float*)d_in[23];
    const float* Wm3 = (const float*)d_in[24];
    const float* bm3 = (const float*)d_in[25];

    int  Nn = in_sizes[0] / DD;
    long E  = in_sizes[1] / 3;

    float* out  = (float*)d_out;
    float* outz = out;
    float* outp = out + (size_t)Nn * DD;

    k_zero<<<2048, 256>>>(Nn);

    long total = E * 16;
    int eblks = (int)((total + 255) / 256);
    k_edge1<<<eblks, 256>>>(x, ei, total);
    k_node1<<<1184, 256>>>(x, Wp1, bp1, Wn1, bn1, Nn);
    k_edge2<<<eblks, 256>>>(ei, total);
    k_node2a<<<1184, 256>>>(Wp2, bp2, Wn2, bn2, Ww, bw, outz, Nn);
    k_node2b<<<1184, 256>>>(Wm1, bm1, g1, be1, rm1, rv1,
                            Wm2, bm2, g2, be2, rm2, rv2,
                            Wm3, bm3, outz, outp, Nn);
}

// round 3
// speedup vs baseline: 1.1025x; 1.1025x over previous
#include <cuda_runtime.h>
#include <math.h>

#define NMAX 100000
#define DD 64
#define HH 32

// -------- persistent scratch (device globals; no allocation allowed) --------
__device__ __align__(16) float g_P[NMAX * HH];      // x @ Wp1[:64]
__device__ __align__(16) float g_Q[NMAX * HH];      // x @ Wn1[:64]
__device__ __align__(16) float g_accP[NMAX * HH];   // sum over pos edges of P[src]
__device__ __align__(16) float g_accN[NMAX * HH];   // sum over neg edges of Q[src]
__device__ __align__(16) float g_cntp[NMAX];
__device__ __align__(16) float g_cntn[NMAX];
__device__ __align__(16) float g_xpn[NMAX * DD];    // [xp | xn] packed per node
__device__ __align__(16) float g_accP2[NMAX * DD];  // pos edges: [sum xp | sum xn]
__device__ __align__(16) float g_accN2[NMAX * DD];  // neg edges: [sum xn | sum xp]

__device__ __forceinline__ void red_v4(float* p, float4 v) {
    asm volatile("red.global.add.v4.f32 [%0], {%1,%2,%3,%4};"
                 :: "l"(p), "f"(v.x), "f"(v.y), "f"(v.z), "f"(v.w)
                 : "memory");
}

// -------------------------------- zeroing ----------------------------------
__global__ void k_zero(int n) {
    size_t i = (size_t)blockIdx.x * blockDim.x + threadIdx.x;
    size_t stride = (size_t)gridDim.x * blockDim.x;
    float4 z4 = make_float4(0.f, 0.f, 0.f, 0.f);
    size_t nh = (size_t)n * HH / 4;
    for (size_t j = i; j < nh; j += stride) {
        ((float4*)g_accP)[j] = z4;
        ((float4*)g_accN)[j] = z4;
    }
    size_t nd = (size_t)n * DD / 4;
    for (size_t j = i; j < nd; j += stride) {
        ((float4*)g_accP2)[j] = z4;
        ((float4*)g_accN2)[j] = z4;
    }
    size_t nc = (size_t)n / 4;
    for (size_t j = i; j < nc; j += stride) {
        ((float4*)g_cntp)[j] = z4;
        ((float4*)g_cntn)[j] = z4;
    }
}

// ------------------------- projection: P = x@Wp1_top, Q = x@Wn1_top ---------
__global__ void k_proj1(const float* __restrict__ x,
                        const float* __restrict__ Wp1,
                        const float* __restrict__ Wn1, int n_nodes) {
    __shared__ float Wp[64 * 32], Wn[64 * 32];
    int tid = threadIdx.x;
    for (int i = tid; i < 64 * 32; i += blockDim.x) {
        Wp[i] = Wp1[i];          // rows 0..63 of Wp1
        Wn[i] = Wn1[i];          // rows 0..63 of Wn1
    }
    __syncthreads();

    int lane = tid & 31, w = tid >> 5;
    for (int n = blockIdx.x * 8 + w; n < n_nodes; n += gridDim.x * 8) {
        size_t nb = (size_t)n * 64;
        float x0 = x[nb + lane];
        float x1 = x[nb + 32 + lane];
        float accp = 0.f, accq = 0.f;
#pragma unroll
        for (int k = 0; k < 32; k++) {
            float u0 = __shfl_sync(0xffffffffu, x0, k);
            float u1 = __shfl_sync(0xffffffffu, x1, k);
            accp += u0 * Wp[k * 32 + lane] + u1 * Wp[(32 + k) * 32 + lane];
            accq += u0 * Wn[k * 32 + lane] + u1 * Wn[(32 + k) * 32 + lane];
        }
        g_P[(size_t)n * 32 + lane] = accp;
        g_Q[(size_t)n * 32 + lane] = accq;
    }
}

// --------------------------- layer-1 aggregation ----------------------------
// 8 threads per edge, each one float4 chunk of the 32-dim projected vector.
__global__ void k_edge1(const int* __restrict__ ei, long total) {
    long idx = (long)blockIdx.x * blockDim.x + threadIdx.x;
    if (idx >= total) return;
    int e = (int)(idx >> 3);
    int c = (int)(idx & 7);
    long eb = 3L * e;
    int s  = __ldg(ei + eb);
    int d  = __ldg(ei + eb + 1);
    int sg = __ldg(ei + eb + 2);
    const float* srcb = (sg > 0) ? g_P : g_Q;
    float*       dstb = (sg > 0) ? g_accP : g_accN;
    float4 v = *(const float4*)(srcb + (size_t)s * HH + c * 4);
    red_v4(dstb + (size_t)d * HH + c * 4, v);
    if (c == 0) atomicAdd((sg > 0) ? (g_cntp + d) : (g_cntn + d), 1.0f);
}

// ------------------------------- node layer 1 -------------------------------
// hp = accP/cntp + x@Wp1[64:] + bp1 ; hn = accN/cntn + x@Wn1[64:] + bn1
// writes xpn = [tanh(hp) | tanh(hn)]
__global__ void k_node1(const float* __restrict__ x,
                        const float* __restrict__ Wp1, const float* __restrict__ bp1,
                        const float* __restrict__ Wn1, const float* __restrict__ bn1,
                        int n_nodes) {
    __shared__ float Wp[64 * 32], Wn[64 * 32], bp[32], bn[32];
    int tid = threadIdx.x;
    for (int i = tid; i < 64 * 32; i += blockDim.x) {
        Wp[i] = Wp1[64 * 32 + i];   // rows 64..127
        Wn[i] = Wn1[64 * 32 + i];
    }
    if (tid < 32) { bp[tid] = bp1[tid]; bn[tid] = bn1[tid]; }
    __syncthreads();

    int lane = tid & 31, w = tid >> 5;
    for (int n = blockIdx.x * 8 + w; n < n_nodes; n += gridDim.x * 8) {
        float invp = 1.0f / fmaxf(g_cntp[n], 1.0f);
        float invn = 1.0f / fmaxf(g_cntn[n], 1.0f);
        size_t nb = (size_t)n * 64;
        float x0 = x[nb + lane];
        float x1 = x[nb + 32 + lane];
        float accp = bp[lane] + g_accP[(size_t)n * 32 + lane] * invp;
        float accn = bn[lane] + g_accN[(size_t)n * 32 + lane] * invn;
#pragma unroll
        for (int k = 0; k < 32; k++) {
            float u0 = __shfl_sync(0xffffffffu, x0, k);
            float u1 = __shfl_sync(0xffffffffu, x1, k);
            accp += u0 * Wp[k * 32 + lane] + u1 * Wp[(32 + k) * 32 + lane];
            accn += u0 * Wn[k * 32 + lane] + u1 * Wn[(32 + k) * 32 + lane];
        }
        g_xpn[nb + lane]      = tanhf(accp);
        g_xpn[nb + 32 + lane] = tanhf(accn);
    }
}

// --------------------------- layer-2 aggregation ----------------------------
// 16 threads per edge: contiguous 256B gather of xpn[src] = [xp|xn].
// pos: same chunk -> accP2 = [sum xp | sum xn]
// neg: half-swapped -> accN2 = [sum xn | sum xp]
__global__ void k_edge2(const int* __restrict__ ei, long total) {
    long idx = (long)blockIdx.x * blockDim.x + threadIdx.x;
    if (idx >= total) return;
    int e = (int)(idx >> 4);
    int c = (int)(idx & 15);
    long eb = 3L * e;
    int s  = __ldg(ei + eb);
    int d  = __ldg(ei + eb + 1);
    int sg = __ldg(ei + eb + 2);
    float4 v = *(const float4*)(g_xpn + (size_t)s * DD + c * 4);
    if (sg > 0) {
        red_v4(g_accP2 + (size_t)d * DD + c * 4, v);
    } else {
        int cs = (c + 8) & 15;
        red_v4(g_accN2 + (size_t)d * DD + cs * 4, v);
    }
}

// ---------------------- node layer 2 + MLP head (fused) ---------------------
// hp2 = accP2[:32]/cp + accN2[:32]/cn + xp@Wp2[64:] + bp2
// hn2 = accP2[32:]/cp + accN2[32:]/cn + xn@Wn2[64:] + bn2   (wait: see mapping)
// Actually: accP2 = [A=mean_pos(xp) | C=mean_pos(xn)], accN2 = [B=mean_neg(xn) | D=mean_neg(xp)]
// hp2 = A@Wp2[:32] + B@Wp2[32:64] + xp@Wp2[64:96] + bp2
// hn2 = C@Wn2[:32] + D@Wn2[32:64] + xn@Wn2[64:96] + bn2
// z = tanh(tanh([hp2|hn2]) @ Ww + bw) -> out; then BN-folded MLP head -> prob
__global__ void __launch_bounds__(256)
k_node2(const float* __restrict__ Wp2, const float* __restrict__ bp2,
        const float* __restrict__ Wn2, const float* __restrict__ bn2,
        const float* __restrict__ Ww,  const float* __restrict__ bw,
        const float* __restrict__ Wm1, const float* __restrict__ bm1,
        const float* __restrict__ g1,  const float* __restrict__ be1,
        const float* __restrict__ rm1, const float* __restrict__ rv1,
        const float* __restrict__ Wm2, const float* __restrict__ bm2,
        const float* __restrict__ g2,  const float* __restrict__ be2,
        const float* __restrict__ rm2, const float* __restrict__ rv2,
        const float* __restrict__ Wm3, const float* __restrict__ bm3,
        float* __restrict__ outz, float* __restrict__ outp, int n_nodes) {
    extern __shared__ float sm[];
    float* Wp  = sm;                 // 96*32
    float* Wn  = Wp + 96 * 32;       // 96*32
    float* W3  = Wn + 96 * 32;       // 64*64  (Ww)
    float* W1  = W3 + 64 * 64;       // 64*64  (Wm1)
    float* W2  = W1 + 64 * 64;       // 64*64  (Wm2)
    float* bp  = W2 + 64 * 64;       // 32
    float* bn  = bp + 32;            // 32
    float* bwv = bn + 32;            // 64
    float* sc1 = bwv + 64;           // 64
    float* of1 = sc1 + 64;           // 64
    float* sc2 = of1 + 64;           // 64
    float* of2 = sc2 + 64;           // 64
    float* w3v = of2 + 64;           // 64
    float* b3  = w3v + 64;           // 1

    int tid = threadIdx.x;
    for (int i = tid; i < 96 * 32; i += blockDim.x) { Wp[i] = Wp2[i]; Wn[i] = Wn2[i]; }
    for (int i = tid; i < 64 * 64; i += blockDim.x) {
        W3[i] = Ww[i]; W1[i] = Wm1[i]; W2[i] = Wm2[i];
    }
    if (tid < 32) { bp[tid] = bp2[tid]; bn[tid] = bn2[tid]; }
    if (tid < 64) {
        bwv[tid] = bw[tid];
        float s1 = g1[tid] * rsqrtf(rv1[tid] + 1e-5f);
        sc1[tid] = s1;
        of1[tid] = (bm1[tid] - rm1[tid]) * s1 + be1[tid];
        float s2 = g2[tid] * rsqrtf(rv2[tid] + 1e-5f);
        sc2[tid] = s2;
        of2[tid] = (bm2[tid] - rm2[tid]) * s2 + be2[tid];
        w3v[tid] = Wm3[tid];
    }
    if (tid == 0) b3[0] = bm3[0];
    __syncthreads();

    int lane = tid & 31, w = tid >> 5;
    for (int n = blockIdx.x * 8 + w; n < n_nodes; n += gridDim.x * 8) {
        float invp = 1.0f / fmaxf(g_cntp[n], 1.0f);
        float invn = 1.0f / fmaxf(g_cntn[n], 1.0f);
        size_t nb = (size_t)n * 64;
        float Av = g_accP2[nb + lane]      * invp;  // mean_pos(xp)
        float Cv = g_accP2[nb + 32 + lane] * invp;  // mean_pos(xn)
        float Bv = g_accN2[nb + lane]      * invn;  // mean_neg(xn)
        float Dv = g_accN2[nb + 32 + lane] * invn;  // mean_neg(xp)
        float Xp = g_xpn[nb + lane];
        float Xn = g_xpn[nb + 32 + lane];
        float accp = bp[lane], accn = bn[lane];
#pragma unroll
        for (int k = 0; k < 32; k++) {
            float av = __shfl_sync(0xffffffffu, Av, k);
            float bv = __shfl_sync(0xffffffffu, Bv, k);
            float pv = __shfl_sync(0xffffffffu, Xp, k);
            float cv = __shfl_sync(0xffffffffu, Cv, k);
            float dv = __shfl_sync(0xffffffffu, Dv, k);
            float nv = __shfl_sync(0xffffffffu, Xn, k);
            accp += av * Wp[k * 32 + lane] + bv * Wp[(32 + k) * 32 + lane]
                  + pv * Wp[(64 + k) * 32 + lane];
            accn += cv * Wn[k * 32 + lane] + dv * Wn[(32 + k) * 32 + lane]
                  + nv * Wn[(64 + k) * 32 + lane];
        }
        float zl = tanhf(accp), zh = tanhf(accn);
        float acc0 = bwv[lane], acc1 = bwv[32 + lane];
#pragma unroll
        for (int k = 0; k < 32; k++) {
            float u = __shfl_sync(0xffffffffu, zl, k);
            float v = __shfl_sync(0xffffffffu, zh, k);
            acc0 += u * W3[k * 64 + lane]      + v * W3[(32 + k) * 64 + lane];
            acc1 += u * W3[k * 64 + 32 + lane] + v * W3[(32 + k) * 64 + 32 + lane];
        }
        float z0 = tanhf(acc0), z1 = tanhf(acc1);
        outz[nb + lane]      = z0;
        outz[nb + 32 + lane] = z1;

        // ---- MLP head (BN folded) ----
        float t0 = 0.f, t1 = 0.f;
#pragma unroll
        for (int k = 0; k < 32; k++) {
            float u = __shfl_sync(0xffffffffu, z0, k);
            float v = __shfl_sync(0xffffffffu, z1, k);
            t0 += u * W1[k * 64 + lane]      + v * W1[(32 + k) * 64 + lane];
            t1 += u * W1[k * 64 + 32 + lane] + v * W1[(32 + k) * 64 + 32 + lane];
        }
        float h0 = fmaxf(t0 * sc1[lane] + of1[lane], 0.f);
        float h1 = fmaxf(t1 * sc1[32 + lane] + of1[32 + lane], 0.f);
        float q0 = 0.f, q1 = 0.f;
#pragma unroll
        for (int k = 0; k < 32; k++) {
            float u = __shfl_sync(0xffffffffu, h0, k);
            float v = __shfl_sync(0xffffffffu, h1, k);
            q0 += u * W2[k * 64 + lane]      + v * W2[(32 + k) * 64 + lane];
            q1 += u * W2[k * 64 + 32 + lane] + v * W2[(32 + k) * 64 + 32 + lane];
        }
        float r0 = fmaxf(q0 * sc2[lane] + of2[lane], 0.f);
        float r1 = fmaxf(q1 * sc2[32 + lane] + of2[32 + lane], 0.f);
        float part = r0 * w3v[lane] + r1 * w3v[32 + lane];
#pragma unroll
        for (int o = 16; o; o >>= 1)
            part += __shfl_down_sync(0xffffffffu, part, o);
        if (lane == 0)
            outp[n] = 1.0f / (1.0f + expf(-(part + b3[0])));
    }
}

// -------------------------------- launcher ----------------------------------
extern "C" void kernel_launch(void* const* d_in, const int* in_sizes, int n_in,
                              void* d_out, int out_size) {
    const float* x   = (const float*)d_in[0];
    const int*   ei  = (const int*)d_in[1];
    const float* Wp1 = (const float*)d_in[2];
    const float* bp1 = (const float*)d_in[3];
    const float* Wn1 = (const float*)d_in[4];
    const float* bn1 = (const float*)d_in[5];
    const float* Wp2 = (const float*)d_in[6];
    const float* bp2 = (const float*)d_in[7];
    const float* Wn2 = (const float*)d_in[8];
    const float* bn2 = (const float*)d_in[9];
    const float* Ww  = (const float*)d_in[10];
    const float* bw  = (const float*)d_in[11];
    const float* Wm1 = (const float*)d_in[12];
    const float* bm1 = (const float*)d_in[13];
    const float* g1  = (const float*)d_in[14];
    const float* be1 = (const float*)d_in[15];
    const float* rm1 = (const float*)d_in[16];
    const float* rv1 = (const float*)d_in[17];
    const float* Wm2 = (const float*)d_in[18];
    const float* bm2 = (const float*)d_in[19];
    const float* g2  = (const float*)d_in[20];
    const float* be2 = (const float*)d_in[21];
    const float* rm2 = (const float*)d_in[22];
    const float* rv2 = (const float*)d_in[23];
    const float* Wm3 = (const float*)d_in[24];
    const float* bm3 = (const float*)d_in[25];

    int  Nn = in_sizes[0] / DD;
    long E  = in_sizes[1] / 3;

    float* out  = (float*)d_out;
    float* outz = out;
    float* outp = out + (size_t)Nn * DD;

    // fused node2 needs >48KB dynamic smem
    const int NODE2_SMEM = (96 * 32 * 2 + 64 * 64 * 3 + 32 * 2 + 64 * 6 + 16) * 4;
    cudaFuncSetAttribute(k_node2, cudaFuncAttributeMaxDynamicSharedMemorySize,
                         NODE2_SMEM);

    k_zero<<<2048, 256>>>(Nn);
    k_proj1<<<1184, 256>>>(x, Wp1, Wn1, Nn);

    long t1 = E * 8;
    k_edge1<<<(int)((t1 + 255) / 256), 256>>>(ei, t1);

    k_node1<<<1184, 256>>>(x, Wp1, bp1, Wn1, bn1, Nn);

    long t2 = E * 16;
    k_edge2<<<(int)((t2 + 255) / 256), 256>>>(ei, t2);

    k_node2<<<444, 256, NODE2_SMEM>>>(Wp2, bp2, Wn2, bn2, Ww, bw,
                                      Wm1, bm1, g1, be1, rm1, rv1,
                                      Wm2, bm2, g2, be2, rm2, rv2,
                                      Wm3, bm3, outz, outp, Nn);
}

// round 4
// speedup vs baseline: 1.6219x; 1.4711x over previous
#include <cuda_runtime.h>
#include <math.h>

#define NMAX 100000
#define DD 64
#define HH 32
typedef unsigned long long u64;

// -------- persistent scratch (device globals; no allocation allowed) --------
__device__ __align__(16) float g_P[NMAX * HH];      // x @ Wp1[:64]
__device__ __align__(16) float g_Q[NMAX * HH];      // x @ Wn1[:64]
__device__ __align__(16) float g_RS[NMAX * DD];     // [x@Wp1[64:]+bp1 | x@Wn1[64:]+bn1]
__device__ __align__(16) float g_accP[NMAX * HH];   // sum over pos edges of P[src]
__device__ __align__(16) float g_accN[NMAX * HH];   // sum over neg edges of Q[src]
__device__ __align__(16) float g_cntp[NMAX];
__device__ __align__(16) float g_cntn[NMAX];
__device__ __align__(16) float g_xpn[NMAX * DD];    // [xp | xn] packed per node
__device__ __align__(16) float g_accP2[NMAX * DD];  // pos edges: [sum xp | sum xn]
__device__ __align__(16) float g_accN2[NMAX * DD];  // neg edges: [sum xn | sum xp]

// ------------------------------ tiny helpers --------------------------------
__device__ __forceinline__ void red_v4(float* p, float4 v) {
    asm volatile("red.global.add.v4.f32 [%0], {%1,%2,%3,%4};"
                 :: "l"(p), "f"(v.x), "f"(v.y), "f"(v.z), "f"(v.w)
                 : "memory");
}
__device__ __forceinline__ u64 fma2(u64 a, u64 b, u64 c) {
    u64 d;
    asm("fma.rn.f32x2 %0, %1, %2, %3;" : "=l"(d) : "l"(a), "l"(b), "l"(c));
    return d;
}
__device__ __forceinline__ u64 dup2(float a) {
    u64 r;
    asm("mov.b64 %0, {%1, %1};" : "=l"(r) : "f"(a));
    return r;
}
__device__ __forceinline__ float2 unpack2(u64 v) {
    float2 r;
    asm("mov.b64 {%0, %1}, %2;" : "=f"(r.x), "=f"(r.y) : "l"(v));
    return r;
}
// acc[16] covers 32 outputs; wrow = 32-float weight row (broadcast LDS.128)
__device__ __forceinline__ void fma_row32(u64* acc, const float* wrow, u64 s2) {
#pragma unroll
    for (int q = 0; q < 8; q++) {
        ulonglong2 w = *(const ulonglong2*)(wrow + 4 * q);
        acc[2 * q]     = fma2(s2, w.x, acc[2 * q]);
        acc[2 * q + 1] = fma2(s2, w.y, acc[2 * q + 1]);
    }
}
// acc[32] covers 64 outputs; wrow = 64-float weight row
__device__ __forceinline__ void fma_row64(u64* acc, const float* wrow, u64 s2) {
#pragma unroll
    for (int q = 0; q < 16; q++) {
        ulonglong2 w = *(const ulonglong2*)(wrow + 4 * q);
        acc[2 * q]     = fma2(s2, w.x, acc[2 * q]);
        acc[2 * q + 1] = fma2(s2, w.y, acc[2 * q + 1]);
    }
}

// -------------------------------- zeroing ----------------------------------
__global__ void k_zero(int n) {
    size_t i = (size_t)blockIdx.x * blockDim.x + threadIdx.x;
    size_t stride = (size_t)gridDim.x * blockDim.x;
    float4 z4 = make_float4(0.f, 0.f, 0.f, 0.f);
    size_t nh = (size_t)n * HH / 4;
    for (size_t j = i; j < nh; j += stride) {
        ((float4*)g_accP)[j] = z4;
        ((float4*)g_accN)[j] = z4;
    }
    size_t nd = (size_t)n * DD / 4;
    for (size_t j = i; j < nd; j += stride) {
        ((float4*)g_accP2)[j] = z4;
        ((float4*)g_accN2)[j] = z4;
    }
    size_t nc = (size_t)n / 4;
    for (size_t j = i; j < nc; j += stride) {
        ((float4*)g_cntp)[j] = z4;
        ((float4*)g_cntn)[j] = z4;
    }
}

// ----------------- projection: P,Q (agg operands) and R,S (self term) -------
// P = x@Wp1[:64]; Q = x@Wn1[:64]; R = x@Wp1[64:]+bp1; S = x@Wn1[64:]+bn1
__global__ void __launch_bounds__(256)
k_proj1(const float* __restrict__ x,
        const float* __restrict__ Wp1, const float* __restrict__ bp1,
        const float* __restrict__ Wn1, const float* __restrict__ bn1,
        int n_nodes) {
    __shared__ __align__(16) float Wp[128 * 32], Wn[128 * 32];
    __shared__ __align__(16) float bps[32], bns[32];
    int tid = threadIdx.x;
    for (int i = tid; i < 128 * 32; i += blockDim.x) {
        Wp[i] = Wp1[i];
        Wn[i] = Wn1[i];
    }
    if (tid < 32) { bps[tid] = bp1[tid]; bns[tid] = bn1[tid]; }
    __syncthreads();

    int n = blockIdx.x * blockDim.x + tid;
    if (n >= n_nodes) return;

    const float4* x4 = (const float4*)x + (size_t)n * 16;

    // phase A: rows 0..63 -> P, Q
    {
        u64 aP[16], aQ[16];
#pragma unroll
        for (int jp = 0; jp < 16; jp++) { aP[jp] = 0ull; aQ[jp] = 0ull; }
        for (int kc = 0; kc < 16; kc++) {
            float4 xv = x4[kc];
            const float* xa = (const float*)&xv;
#pragma unroll
            for (int e = 0; e < 4; e++) {
                int k = kc * 4 + e;
                u64 x2 = dup2(xa[e]);
                fma_row32(aP, Wp + k * 32, x2);
                fma_row32(aQ, Wn + k * 32, x2);
            }
        }
        ulonglong2* Pd = (ulonglong2*)(g_P + (size_t)n * 32);
        ulonglong2* Qd = (ulonglong2*)(g_Q + (size_t)n * 32);
#pragma unroll
        for (int q = 0; q < 8; q++) {
            Pd[q] = make_ulonglong2(aP[2 * q], aP[2 * q + 1]);
            Qd[q] = make_ulonglong2(aQ[2 * q], aQ[2 * q + 1]);
        }
    }
    // phase B: rows 64..127 + bias -> R, S
    {
        u64 aR[16], aS[16];
        const u64* bp2 = (const u64*)bps;
        const u64* bn2 = (const u64*)bns;
#pragma unroll
        for (int jp = 0; jp < 16; jp++) { aR[jp] = bp2[jp]; aS[jp] = bn2[jp]; }
        for (int kc = 0; kc < 16; kc++) {
            float4 xv = x4[kc];
            const float* xa = (const float*)&xv;
#pragma unroll
            for (int e = 0; e < 4; e++) {
                int k = 64 + kc * 4 + e;
                u64 x2 = dup2(xa[e]);
                fma_row32(aR, Wp + k * 32, x2);
                fma_row32(aS, Wn + k * 32, x2);
            }
        }
        ulonglong2* Rd = (ulonglong2*)(g_RS + (size_t)n * 64);
#pragma unroll
        for (int q = 0; q < 8; q++) {
            Rd[q]     = make_ulonglong2(aR[2 * q], aR[2 * q + 1]);
            Rd[q + 8] = make_ulonglong2(aS[2 * q], aS[2 * q + 1]);
        }
    }
}

// --------------------------- layer-1 aggregation ----------------------------
__global__ void k_edge1(const int* __restrict__ ei, long total) {
    long idx = (long)blockIdx.x * blockDim.x + threadIdx.x;
    if (idx >= total) return;
    int e = (int)(idx >> 3);
    int c = (int)(idx & 7);
    long eb = 3L * e;
    int s  = __ldg(ei + eb);
    int d  = __ldg(ei + eb + 1);
    int sg = __ldg(ei + eb + 2);
    const float* srcb = (sg > 0) ? g_P : g_Q;
    float*       dstb = (sg > 0) ? g_accP : g_accN;
    float4 v = *(const float4*)(srcb + (size_t)s * HH + c * 4);
    red_v4(dstb + (size_t)d * HH + c * 4, v);
    if (c == 0) atomicAdd((sg > 0) ? (g_cntp + d) : (g_cntn + d), 1.0f);
}

// --------------------- node layer 1: elementwise tanh -----------------------
// xpn[n][j] = tanh(RS[n][j] + acc/cnt)
__global__ void k_node1e(long total) {
    long idx = (long)blockIdx.x * blockDim.x + threadIdx.x;
    if (idx >= total) return;
    int n = (int)(idx >> 4);
    int c = (int)(idx & 15);
    float4 rs = ((const float4*)g_RS)[idx];
    float4 acc;
    float inv;
    if (c < 8) {
        acc = ((const float4*)g_accP)[(size_t)n * 8 + c];
        inv = 1.0f / fmaxf(g_cntp[n], 1.0f);
    } else {
        acc = ((const float4*)g_accN)[(size_t)n * 8 + (c - 8)];
        inv = 1.0f / fmaxf(g_cntn[n], 1.0f);
    }
    float4 o;
    o.x = tanhf(rs.x + acc.x * inv);
    o.y = tanhf(rs.y + acc.y * inv);
    o.z = tanhf(rs.z + acc.z * inv);
    o.w = tanhf(rs.w + acc.w * inv);
    ((float4*)g_xpn)[idx] = o;
}

// --------------------------- layer-2 aggregation ----------------------------
// pos: same chunk -> accP2 = [sum xp | sum xn]
// neg: half-swapped -> accN2 = [sum xn | sum xp]
__global__ void k_edge2(const int* __restrict__ ei, long total) {
    long idx = (long)blockIdx.x * blockDim.x + threadIdx.x;
    if (idx >= total) return;
    int e = (int)(idx >> 4);
    int c = (int)(idx & 15);
    long eb = 3L * e;
    int s  = __ldg(ei + eb);
    int d  = __ldg(ei + eb + 1);
    int sg = __ldg(ei + eb + 2);
    float4 v = *(const float4*)(g_xpn + (size_t)s * DD + c * 4);
    if (sg > 0) {
        red_v4(g_accP2 + (size_t)d * DD + c * 4, v);
    } else {
        int cs = (c + 8) & 15;
        red_v4(g_accN2 + (size_t)d * DD + cs * 4, v);
    }
}

// ---------------- node layer 2 + MLP head (fused, thread-per-node) ----------
// A = accP2[:32]/cp, C = accP2[32:]/cp, B = accN2[:32]/cn, D = accN2[32:]/cn
// hp = A@Wp2[:32] + B@Wp2[32:64] + xp@Wp2[64:96] + bp2
// hn = C@Wn2[:32] + D@Wn2[32:64] + xn@Wn2[64:96] + bn2
// z = tanh(tanh([hp|hn])@Ww + bw); prob = MLP head with BN folded
__global__ void __launch_bounds__(128)
k_node2(const float* __restrict__ Wp2, const float* __restrict__ bp2,
        const float* __restrict__ Wn2, const float* __restrict__ bn2,
        const float* __restrict__ Ww,  const float* __restrict__ bw,
        const float* __restrict__ Wm1, const float* __restrict__ bm1,
        const float* __restrict__ g1,  const float* __restrict__ be1,
        const float* __restrict__ rm1, const float* __restrict__ rv1,
        const float* __restrict__ Wm2, const float* __restrict__ bm2,
        const float* __restrict__ g2,  const float* __restrict__ be2,
        const float* __restrict__ rm2, const float* __restrict__ rv2,
        const float* __restrict__ Wm3, const float* __restrict__ bm3,
        float* __restrict__ outz, float* __restrict__ outp, int n_nodes) {
    extern __shared__ __align__(16) float sm[];
    float* Wps  = sm;                  // 96*32
    float* Wns  = Wps + 96 * 32;       // 96*32
    float* Wws  = Wns + 96 * 32;       // 64*64
    float* W1s  = Wws + 64 * 64;       // 64*64
    float* W2s  = W1s + 64 * 64;       // 64*64
    float* bps  = W2s + 64 * 64;       // 32
    float* bns  = bps + 32;            // 32
    float* bws  = bns + 32;            // 64
    float* sc1  = bws + 64;            // 64
    float* of1  = sc1 + 64;            // 64
    float* sc2  = of1 + 64;            // 64
    float* of2  = sc2 + 64;            // 64
    float* w3s  = of2 + 64;            // 64
    float* b3s  = w3s + 64;            // 4 (pad)

    int tid = threadIdx.x;
    for (int i = tid; i < 96 * 32; i += blockDim.x) { Wps[i] = Wp2[i]; Wns[i] = Wn2[i]; }
    for (int i = tid; i < 64 * 64; i += blockDim.x) {
        Wws[i] = Ww[i]; W1s[i] = Wm1[i]; W2s[i] = Wm2[i];
    }
    if (tid < 32) { bps[tid] = bp2[tid]; bns[tid] = bn2[tid]; }
    if (tid < 64) {
        bws[tid] = bw[tid];
        float s1 = g1[tid] * rsqrtf(rv1[tid] + 1e-5f);
        sc1[tid] = s1;
        of1[tid] = (bm1[tid] - rm1[tid]) * s1 + be1[tid];
        float s2 = g2[tid] * rsqrtf(rv2[tid] + 1e-5f);
        sc2[tid] = s2;
        of2[tid] = (bm2[tid] - rm2[tid]) * s2 + be2[tid];
        w3s[tid] = Wm3[tid];
    }
    if (tid == 0) b3s[0] = bm3[0];
    __syncthreads();

    int n = blockIdx.x * blockDim.x + tid;
    if (n >= n_nodes) return;

    float invp = 1.0f / fmaxf(g_cntp[n], 1.0f);
    float invn = 1.0f / fmaxf(g_cntn[n], 1.0f);

    // ---- loop 1: hp/hn (32 outputs each) ----
    u64 hp[16], hn[16];
    const u64* bpp = (const u64*)bps;
    const u64* bnp = (const u64*)bns;
#pragma unroll
    for (int jp = 0; jp < 16; jp++) { hp[jp] = bpp[jp]; hn[jp] = bnp[jp]; }

    const float4* aP4 = (const float4*)g_accP2 + (size_t)n * 16;
    const float4* aN4 = (const float4*)g_accN2 + (size_t)n * 16;
    const float4* xx4 = (const float4*)g_xpn   + (size_t)n * 16;
    for (int kc = 0; kc < 8; kc++) {
        float4 Af = aP4[kc], Cf = aP4[kc + 8];
        float4 Bf = aN4[kc], Df = aN4[kc + 8];
        float4 Pf = xx4[kc], Nf = xx4[kc + 8];
        const float* Aa = (const float*)&Af; const float* Ca = (const float*)&Cf;
        const float* Ba = (const float*)&Bf; const float* Da = (const float*)&Df;
        const float* Pa = (const float*)&Pf; const float* Na = (const float*)&Nf;
#pragma unroll
        for (int e = 0; e < 4; e++) {
            int k = kc * 4 + e;
            u64 a2 = dup2(Aa[e] * invp);
            u64 b2 = dup2(Ba[e] * invn);
            u64 p2 = dup2(Pa[e]);
            fma_row32(hp, Wps + k * 32, a2);
            fma_row32(hp, Wps + (32 + k) * 32, b2);
            fma_row32(hp, Wps + (64 + k) * 32, p2);
            u64 c2 = dup2(Ca[e] * invp);
            u64 d2 = dup2(Da[e] * invn);
            u64 n2 = dup2(Na[e]);
            fma_row32(hn, Wns + k * 32, c2);
            fma_row32(hn, Wns + (32 + k) * 32, d2);
            fma_row32(hn, Wns + (64 + k) * 32, n2);
        }
    }

    float zf[64];
#pragma unroll
    for (int jp = 0; jp < 16; jp++) {
        float2 t = unpack2(hp[jp]);
        zf[2 * jp] = tanhf(t.x); zf[2 * jp + 1] = tanhf(t.y);
        float2 u = unpack2(hn[jp]);
        zf[32 + 2 * jp] = tanhf(u.x); zf[32 + 2 * jp + 1] = tanhf(u.y);
    }

    // ---- loop 2: z = tanh(zf @ Ww + bw) ----
    {
        u64 o[32];
        const u64* bwp = (const u64*)bws;
#pragma unroll
        for (int jp = 0; jp < 32; jp++) o[jp] = bwp[jp];
#pragma unroll
        for (int k = 0; k < 64; k++) fma_row64(o, Wws + k * 64, dup2(zf[k]));
#pragma unroll
        for (int jp = 0; jp < 32; jp++) {
            float2 t = unpack2(o[jp]);
            zf[2 * jp] = tanhf(t.x);
            zf[2 * jp + 1] = tanhf(t.y);
        }
    }
    // store z
    float4* zd = (float4*)(outz + (size_t)n * 64);
#pragma unroll
    for (int q = 0; q < 16; q++)
        zd[q] = make_float4(zf[4 * q], zf[4 * q + 1], zf[4 * q + 2], zf[4 * q + 3]);

    // ---- loop 3: h = relu(bn(zf @ Wm1)) ----
    float hf[64];
    {
        u64 t[32];
#pragma unroll
        for (int jp = 0; jp < 32; jp++) t[jp] = 0ull;
#pragma unroll
        for (int k = 0; k < 64; k++) fma_row64(t, W1s + k * 64, dup2(zf[k]));
#pragma unroll
        for (int jp = 0; jp < 32; jp++) {
            float2 v = unpack2(t[jp]);
            hf[2 * jp]     = fmaxf(v.x * sc1[2 * jp]     + of1[2 * jp],     0.f);
            hf[2 * jp + 1] = fmaxf(v.y * sc1[2 * jp + 1] + of1[2 * jp + 1], 0.f);
        }
    }
    // ---- loop 4: r = relu(bn(hf @ Wm2)); part = dot(r, w3) ----
    float part = 0.f;
    {
        u64 q[32];
#pragma unroll
        for (int jp = 0; jp < 32; jp++) q[jp] = 0ull;
#pragma unroll
        for (int k = 0; k < 64; k++) fma_row64(q, W2s + k * 64, dup2(hf[k]));
#pragma unroll
        for (int jp = 0; jp < 32; jp++) {
            float2 v = unpack2(q[jp]);
            float r0 = fmaxf(v.x * sc2[2 * jp]     + of2[2 * jp],     0.f);
            float r1 = fmaxf(v.y * sc2[2 * jp + 1] + of2[2 * jp + 1], 0.f);
            part += r0 * w3s[2 * jp] + r1 * w3s[2 * jp + 1];
        }
    }
    outp[n] = 1.0f / (1.0f + expf(-(part + b3s[0])));
}

// -------------------------------- launcher ----------------------------------
extern "C" void kernel_launch(void* const* d_in, const int* in_sizes, int n_in,
                              void* d_out, int out_size) {
    const float* x   = (const float*)d_in[0];
    const int*   ei  = (const int*)d_in[1];
    const float* Wp1 = (const float*)d_in[2];
    const float* bp1 = (const float*)d_in[3];
    const float* Wn1 = (const float*)d_in[4];
    const float* bn1 = (const float*)d_in[5];
    const float* Wp2 = (const float*)d_in[6];
    const float* bp2 = (const float*)d_in[7];
    const float* Wn2 = (const float*)d_in[8];
    const float* bn2 = (const float*)d_in[9];
    const float* Ww  = (const float*)d_in[10];
    const float* bw  = (const float*)d_in[11];
    const float* Wm1 = (const float*)d_in[12];
    const float* bm1 = (const float*)d_in[13];
    const float* g1  = (const float*)d_in[14];
    const float* be1 = (const float*)d_in[15];
    const float* rm1 = (const float*)d_in[16];
    const float* rv1 = (const float*)d_in[17];
    const float* Wm2 = (const float*)d_in[18];
    const float* bm2 = (const float*)d_in[19];
    const float* g2  = (const float*)d_in[20];
    const float* be2 = (const float*)d_in[21];
    const float* rm2 = (const float*)d_in[22];
    const float* rv2 = (const float*)d_in[23];
    const float* Wm3 = (const float*)d_in[24];
    const float* bm3 = (const float*)d_in[25];

    int  Nn = in_sizes[0] / DD;
    long E  = in_sizes[1] / 3;

    float* out  = (float*)d_out;
    float* outz = out;
    float* outp = out + (size_t)Nn * DD;

    const int NODE2_SMEM = (96 * 32 * 2 + 64 * 64 * 3 + 32 * 2 + 64 * 6 + 4) * 4;
    cudaFuncSetAttribute(k_node2, cudaFuncAttributeMaxDynamicSharedMemorySize,
                         NODE2_SMEM);

    k_zero<<<2048, 256>>>(Nn);
    k_proj1<<<(Nn + 255) / 256, 256>>>(x, Wp1, bp1, Wn1, bn1, Nn);

    long t1 = E * 8;
    k_edge1<<<(int)((t1 + 255) / 256), 256>>>(ei, t1);

    long tn = (long)Nn * 16;
    k_node1e<<<(int)((tn + 255) / 256), 256>>>(tn);

    long t2 = E * 16;
    k_edge2<<<(int)((t2 + 255) / 256), 256>>>(ei, t2);

    k_node2<<<(Nn + 127) / 128, 128, NODE2_SMEM>>>(
        Wp2, bp2, Wn2, bn2, Ww, bw,
        Wm1, bm1, g1, be1, rm1, rv1,
        Wm2, bm2, g2, be2, rm2, rv2,
        Wm3, bm3, outz, outp, Nn);
}

// round 5
// speedup vs baseline: 1.9582x; 1.2074x over previous
#include <cuda_runtime.h>
#include <cuda_fp16.h>
#include <math.h>

#define NMAX 100000
#define EMAX 1310720
#define DD 64
typedef unsigned long long u64;

// -------- persistent scratch (device globals; no allocation allowed) --------
__device__ __align__(16) __half g_Ph[NMAX * 32];     // x @ Wp1[:64]  (fp16)
__device__ __align__(16) __half g_Qh[NMAX * 32];     // x @ Wn1[:64]  (fp16)
__device__ __align__(16) __half g_accPh[NMAX * 32];  // fp16 accumulators
__device__ __align__(16) __half g_accNh[NMAX * 32];
__device__ __align__(16) __half g_xpnh[NMAX * 64];   // [xp | xn] fp16
__device__ __align__(16) __half g_accP2h[NMAX * 64]; // pos: [sum xp | sum xn]
__device__ __align__(16) __half g_accN2h[NMAX * 64]; // neg: [sum xn | sum xp]
__device__ __align__(16) float  g_cntp[NMAX];
__device__ __align__(16) float  g_cntn[NMAX];
__device__ __align__(16) int2   g_es[EMAX];          // {src, dst or ~dst(neg)}

// ------------------------------ tiny helpers --------------------------------
__device__ __forceinline__ void red_v4h(__half* p, uint4 v) {
    asm volatile("red.global.add.noftz.v4.f16x2 [%0], {%1,%2,%3,%4};"
                 :: "l"(p), "r"(v.x), "r"(v.y), "r"(v.z), "r"(v.w)
                 : "memory");
}
__device__ __forceinline__ u64 fma2(u64 a, u64 b, u64 c) {
    u64 d;
    asm("fma.rn.f32x2 %0, %1, %2, %3;" : "=l"(d) : "l"(a), "l"(b), "l"(c));
    return d;
}
__device__ __forceinline__ u64 dup2(float a) {
    u64 r;
    asm("mov.b64 %0, {%1, %1};" : "=l"(r) : "f"(a));
    return r;
}
__device__ __forceinline__ float2 unpack2(u64 v) {
    float2 r;
    asm("mov.b64 {%0, %1}, %2;" : "=f"(r.x), "=f"(r.y) : "l"(v));
    return r;
}
// convert 8 packed halves (uint4) -> 8 floats
__device__ __forceinline__ void h8tof(uint4 v, float* o) {
    const __half2* h = (const __half2*)&v;
#pragma unroll
    for (int j = 0; j < 4; j++) {
        float2 f = __half22float2(h[j]);
        o[2 * j] = f.x;
        o[2 * j + 1] = f.y;
    }
}
__device__ __forceinline__ unsigned pack_h2(float a, float b) {
    __half2 h = __floats2half2_rn(a, b);
    return *(unsigned*)&h;
}
// acc[16] covers 32 outputs; wrow = 32-float weight row (broadcast LDS.128)
__device__ __forceinline__ void fma_row32(u64* acc, const float* wrow, u64 s2) {
#pragma unroll
    for (int q = 0; q < 8; q++) {
        ulonglong2 w = *(const ulonglong2*)(wrow + 4 * q);
        acc[2 * q]     = fma2(s2, w.x, acc[2 * q]);
        acc[2 * q + 1] = fma2(s2, w.y, acc[2 * q + 1]);
    }
}
// acc[32] covers 64 outputs
__device__ __forceinline__ void fma_row64(u64* acc, const float* wrow, u64 s2) {
#pragma unroll
    for (int q = 0; q < 16; q++) {
        ulonglong2 w = *(const ulonglong2*)(wrow + 4 * q);
        acc[2 * q]     = fma2(s2, w.x, acc[2 * q]);
        acc[2 * q + 1] = fma2(s2, w.y, acc[2 * q + 1]);
    }
}

// -------------------------------- zeroing ----------------------------------
__global__ void k_zero(int n) {
    size_t i = (size_t)blockIdx.x * blockDim.x + threadIdx.x;
    size_t stride = (size_t)gridDim.x * blockDim.x;
    uint4 z4 = make_uint4(0u, 0u, 0u, 0u);
    size_t nh = (size_t)n * 4;   // 32 halves = 4 uint4 per node
    for (size_t j = i; j < nh; j += stride) {
        ((uint4*)g_accPh)[j] = z4;
        ((uint4*)g_accNh)[j] = z4;
    }
    size_t nd = (size_t)n * 8;   // 64 halves = 8 uint4 per node
    for (size_t j = i; j < nd; j += stride) {
        ((uint4*)g_accP2h)[j] = z4;
        ((uint4*)g_accN2h)[j] = z4;
    }
    size_t nc = (size_t)n / 4;
    for (size_t j = i; j < nc; j += stride) {
        ((uint4*)g_cntp)[j] = z4;
        ((uint4*)g_cntn)[j] = z4;
    }
}

// ------------------------- edge packing: {src, dst or ~dst} -----------------
__global__ void k_pack(const int* __restrict__ ei, int E) {
    int e = blockIdx.x * blockDim.x + threadIdx.x;
    if (e >= E) return;
    long eb = 3L * e;
    int s  = __ldg(ei + eb);
    int d  = __ldg(ei + eb + 1);
    int sg = __ldg(ei + eb + 2);
    g_es[e] = make_int2(s, (sg > 0) ? d : ~d);
}

// ----------------- projection: P = x@Wp1[:64], Q = x@Wn1[:64] (fp16 out) ----
__global__ void __launch_bounds__(256)
k_proj1(const float* __restrict__ x,
        const float* __restrict__ Wp1, const float* __restrict__ Wn1,
        int n_nodes) {
    __shared__ __align__(16) float Wp[64 * 32], Wn[64 * 32];
    int tid = threadIdx.x;
    for (int i = tid; i < 64 * 32; i += blockDim.x) {
        Wp[i] = Wp1[i];
        Wn[i] = Wn1[i];
    }
    __syncthreads();

    int n = blockIdx.x * blockDim.x + tid;
    if (n >= n_nodes) return;

    const float4* x4 = (const float4*)x + (size_t)n * 16;
    u64 aP[16], aQ[16];
#pragma unroll
    for (int jp = 0; jp < 16; jp++) { aP[jp] = 0ull; aQ[jp] = 0ull; }
    for (int kc = 0; kc < 16; kc++) {
        float4 xv = x4[kc];
        const float* xa = (const float*)&xv;
#pragma unroll
        for (int e = 0; e < 4; e++) {
            int k = kc * 4 + e;
            u64 x2 = dup2(xa[e]);
            fma_row32(aP, Wp + k * 32, x2);
            fma_row32(aQ, Wn + k * 32, x2);
        }
    }
    uint4* Pd = (uint4*)g_Ph + (size_t)n * 4;
    uint4* Qd = (uint4*)g_Qh + (size_t)n * 4;
#pragma unroll
    for (int q = 0; q < 4; q++) {
        uint4 up, uq;
        float2 a0 = unpack2(aP[4 * q]),     a1 = unpack2(aP[4 * q + 1]);
        float2 a2 = unpack2(aP[4 * q + 2]), a3 = unpack2(aP[4 * q + 3]);
        up.x = pack_h2(a0.x, a0.y); up.y = pack_h2(a1.x, a1.y);
        up.z = pack_h2(a2.x, a2.y); up.w = pack_h2(a3.x, a3.y);
        float2 b0 = unpack2(aQ[4 * q]),     b1 = unpack2(aQ[4 * q + 1]);
        float2 b2 = unpack2(aQ[4 * q + 2]), b3 = unpack2(aQ[4 * q + 3]);
        uq.x = pack_h2(b0.x, b0.y); uq.y = pack_h2(b1.x, b1.y);
        uq.z = pack_h2(b2.x, b2.y); uq.w = pack_h2(b3.x, b3.y);
        Pd[q] = up;
        Qd[q] = uq;
    }
}

// --------------------------- layer-1 aggregation ----------------------------
// 4 threads per edge; each moves 16B (8 halves) of the 32-dim payload.
__global__ void k_edge1(long total) {
    long idx = (long)blockIdx.x * blockDim.x + threadIdx.x;
    if (idx >= total) return;
    int e = (int)(idx >> 2);
    int c = (int)(idx & 3);
    int2 sd = __ldg(&g_es[e]);
    int s = sd.x;
    int d = sd.y;
    bool pos = (d >= 0);
    if (!pos) d = ~d;
    const uint4* src = (const uint4*)(pos ? g_Ph : g_Qh) + (size_t)s * 4 + c;
    __half* dst = (pos ? g_accPh : g_accNh) + (size_t)d * 32 + c * 8;
    red_v4h(dst, *src);
    if (c == 0) atomicAdd(pos ? (g_cntp + d) : (g_cntn + d), 1.0f);
}

// ---------------- node layer 1 (fused self-GEMM + mean + tanh) --------------
// xp = tanh(x@Wp1[64:] + bp1 + accP/cntp); xn likewise. Writes xpn fp16.
__global__ void __launch_bounds__(256)
k_node1(const float* __restrict__ x,
        const float* __restrict__ Wp1, const float* __restrict__ bp1,
        const float* __restrict__ Wn1, const float* __restrict__ bn1,
        int n_nodes) {
    __shared__ __align__(16) float Wp[64 * 32], Wn[64 * 32];
    __shared__ __align__(16) float bps[32], bns[32];
    int tid = threadIdx.x;
    for (int i = tid; i < 64 * 32; i += blockDim.x) {
        Wp[i] = Wp1[64 * 32 + i];   // rows 64..127
        Wn[i] = Wn1[64 * 32 + i];
    }
    if (tid < 32) { bps[tid] = bp1[tid]; bns[tid] = bn1[tid]; }
    __syncthreads();

    int n = blockIdx.x * blockDim.x + tid;
    if (n >= n_nodes) return;

    u64 aR[16], aS[16];
    const u64* bpp = (const u64*)bps;
    const u64* bnp = (const u64*)bns;
#pragma unroll
    for (int jp = 0; jp < 16; jp++) { aR[jp] = bpp[jp]; aS[jp] = bnp[jp]; }

    const float4* x4 = (const float4*)x + (size_t)n * 16;
    for (int kc = 0; kc < 16; kc++) {
        float4 xv = x4[kc];
        const float* xa = (const float*)&xv;
#pragma unroll
        for (int e = 0; e < 4; e++) {
            int k = kc * 4 + e;
            u64 x2 = dup2(xa[e]);
            fma_row32(aR, Wp + k * 32, x2);
            fma_row32(aS, Wn + k * 32, x2);
        }
    }

    float invp = 1.0f / fmaxf(g_cntp[n], 1.0f);
    float invn = 1.0f / fmaxf(g_cntn[n], 1.0f);
    const uint4* ap4 = (const uint4*)g_accPh + (size_t)n * 4;
    const uint4* an4 = (const uint4*)g_accNh + (size_t)n * 4;
    uint4* xd = (uint4*)g_xpnh + (size_t)n * 8;
#pragma unroll
    for (int q = 0; q < 4; q++) {
        float av[8], bv[8];
        h8tof(ap4[q], av);
        h8tof(an4[q], bv);
        float rp[8], rn[8];
#pragma unroll
        for (int j = 0; j < 4; j++) {
            float2 t = unpack2(aR[4 * q + j]);
            rp[2 * j]     = tanhf(t.x + av[2 * j] * invp);
            rp[2 * j + 1] = tanhf(t.y + av[2 * j + 1] * invp);
            float2 u = unpack2(aS[4 * q + j]);
            rn[2 * j]     = tanhf(u.x + bv[2 * j] * invn);
            rn[2 * j + 1] = tanhf(u.y + bv[2 * j + 1] * invn);
        }
        uint4 up, un;
        up.x = pack_h2(rp[0], rp[1]); up.y = pack_h2(rp[2], rp[3]);
        up.z = pack_h2(rp[4], rp[5]); up.w = pack_h2(rp[6], rp[7]);
        un.x = pack_h2(rn[0], rn[1]); un.y = pack_h2(rn[2], rn[3]);
        un.z = pack_h2(rn[4], rn[5]); un.w = pack_h2(rn[6], rn[7]);
        xd[q]     = up;   // xp half
        xd[q + 4] = un;   // xn half
    }
}

// --------------------------- layer-2 aggregation ----------------------------
// 8 threads per edge over xpn (64 halves). pos: same chunk -> accP2.
// neg: half-swap (xp chunks -> D region, xn chunks -> B region) -> accN2.
__global__ void k_edge2(long total) {
    long idx = (long)blockIdx.x * blockDim.x + threadIdx.x;
    if (idx >= total) return;
    int e = (int)(idx >> 3);
    int c = (int)(idx & 7);
    int2 sd = __ldg(&g_es[e]);
    int s = sd.x;
    int d = sd.y;
    uint4 v = *((const uint4*)g_xpnh + (size_t)s * 8 + c);
    if (d >= 0) {
        red_v4h(g_accP2h + (size_t)d * 64 + c * 8, v);
    } else {
        d = ~d;
        int cs = (c + 4) & 7;
        red_v4h(g_accN2h + (size_t)d * 64 + cs * 8, v);
    }
}

// ---------------- node layer 2 + MLP head (fused, thread-per-node) ----------
__global__ void __launch_bounds__(128)
k_node2(const float* __restrict__ Wp2, const float* __restrict__ bp2,
        const float* __restrict__ Wn2, const float* __restrict__ bn2,
        const float* __restrict__ Ww,  const float* __restrict__ bw,
        const float* __restrict__ Wm1, const float* __restrict__ bm1,
        const float* __restrict__ g1,  const float* __restrict__ be1,
        const float* __restrict__ rm1, const float* __restrict__ rv1,
        const float* __restrict__ Wm2, const float* __restrict__ bm2,
        const float* __restrict__ g2,  const float* __restrict__ be2,
        const float* __restrict__ rm2, const float* __restrict__ rv2,
        const float* __restrict__ Wm3, const float* __restrict__ bm3,
        float* __restrict__ outz, float* __restrict__ outp, int n_nodes) {
    extern __shared__ __align__(16) float sm[];
    float* Wps  = sm;                  // 96*32
    float* Wns  = Wps + 96 * 32;       // 96*32
    float* Wws  = Wns + 96 * 32;       // 64*64
    float* W1s  = Wws + 64 * 64;       // 64*64
    float* W2s  = W1s + 64 * 64;       // 64*64
    float* bps  = W2s + 64 * 64;       // 32
    float* bns  = bps + 32;            // 32
    float* bws  = bns + 32;            // 64
    float* sc1  = bws + 64;            // 64
    float* of1  = sc1 + 64;            // 64
    float* sc2  = of1 + 64;            // 64
    float* of2  = sc2 + 64;            // 64
    float* w3s  = of2 + 64;            // 64
    float* b3s  = w3s + 64;            // 4 (pad)

    int tid = threadIdx.x;
    for (int i = tid; i < 96 * 32; i += blockDim.x) { Wps[i] = Wp2[i]; Wns[i] = Wn2[i]; }
    for (int i = tid; i < 64 * 64; i += blockDim.x) {
        Wws[i] = Ww[i]; W1s[i] = Wm1[i]; W2s[i] = Wm2[i];
    }
    if (tid < 32) { bps[tid] = bp2[tid]; bns[tid] = bn2[tid]; }
    if (tid < 64) {
        bws[tid] = bw[tid];
        float s1 = g1[tid] * rsqrtf(rv1[tid] + 1e-5f);
        sc1[tid] = s1;
        of1[tid] = (bm1[tid] - rm1[tid]) * s1 + be1[tid];
        float s2 = g2[tid] * rsqrtf(rv2[tid] + 1e-5f);
        sc2[tid] = s2;
        of2[tid] = (bm2[tid] - rm2[tid]) * s2 + be2[tid];
        w3s[tid] = Wm3[tid];
    }
    if (tid == 0) b3s[0] = bm3[0];
    __syncthreads();

    int n = blockIdx.x * blockDim.x + tid;
    if (n >= n_nodes) return;

    float invp = 1.0f / fmaxf(g_cntp[n], 1.0f);
    float invn = 1.0f / fmaxf(g_cntn[n], 1.0f);

    // ---- loop 1: hp/hn (32 outputs each) ----
    u64 hp[16], hn[16];
    const u64* bpp = (const u64*)bps;
    const u64* bnp = (const u64*)bns;
#pragma unroll
    for (int jp = 0; jp < 16; jp++) { hp[jp] = bpp[jp]; hn[jp] = bnp[jp]; }

    const uint4* aP4 = (const uint4*)g_accP2h + (size_t)n * 8;
    const uint4* aN4 = (const uint4*)g_accN2h + (size_t)n * 8;
    const uint4* xx4 = (const uint4*)g_xpnh   + (size_t)n * 8;
    for (int kc = 0; kc < 4; kc++) {
        float Aa[8], Ca[8], Ba[8], Da[8], Pa[8], Na[8];
        h8tof(aP4[kc], Aa);     // A = sum_pos xp
        h8tof(aP4[kc + 4], Ca); // C = sum_pos xn
        h8tof(aN4[kc], Ba);     // B = sum_neg xn
        h8tof(aN4[kc + 4], Da); // D = sum_neg xp
        h8tof(xx4[kc], Pa);     // xp
        h8tof(xx4[kc + 4], Na); // xn
#pragma unroll
        for (int e = 0; e < 8; e++) {
            int k = kc * 8 + e;
            u64 a2 = dup2(Aa[e] * invp);
            u64 b2 = dup2(Ba[e] * invn);
            u64 p2 = dup2(Pa[e]);
            fma_row32(hp, Wps + k * 32, a2);
            fma_row32(hp, Wps + (32 + k) * 32, b2);
            fma_row32(hp, Wps + (64 + k) * 32, p2);
            u64 c2 = dup2(Ca[e] * invp);
            u64 d2 = dup2(Da[e] * invn);
            u64 n2 = dup2(Na[e]);
            fma_row32(hn, Wns + k * 32, c2);
            fma_row32(hn, Wns + (32 + k) * 32, d2);
            fma_row32(hn, Wns + (64 + k) * 32, n2);
        }
    }

    float zf[64];
#pragma unroll
    for (int jp = 0; jp < 16; jp++) {
        float2 t = unpack2(hp[jp]);
        zf[2 * jp] = tanhf(t.x); zf[2 * jp + 1] = tanhf(t.y);
        float2 u = unpack2(hn[jp]);
        zf[32 + 2 * jp] = tanhf(u.x); zf[32 + 2 * jp + 1] = tanhf(u.y);
    }

    // ---- loop 2: z = tanh(zf @ Ww + bw) ----
    {
        u64 o[32];
        const u64* bwp = (const u64*)bws;
#pragma unroll
        for (int jp = 0; jp < 32; jp++) o[jp] = bwp[jp];
#pragma unroll
        for (int k = 0; k < 64; k++) fma_row64(o, Wws + k * 64, dup2(zf[k]));
#pragma unroll
        for (int jp = 0; jp < 32; jp++) {
            float2 t = unpack2(o[jp]);
            zf[2 * jp] = tanhf(t.x);
            zf[2 * jp + 1] = tanhf(t.y);
        }
    }
    // store z
    float4* zd = (float4*)(outz + (size_t)n * 64);
#pragma unroll
    for (int q = 0; q < 16; q++)
        zd[q] = make_float4(zf[4 * q], zf[4 * q + 1], zf[4 * q + 2], zf[4 * q + 3]);

    // ---- loop 3: h = relu(bn(zf @ Wm1)) ----
    float hf[64];
    {
        u64 t[32];
#pragma unroll
        for (int jp = 0; jp < 32; jp++) t[jp] = 0ull;
#pragma unroll
        for (int k = 0; k < 64; k++) fma_row64(t, W1s + k * 64, dup2(zf[k]));
#pragma unroll
        for (int jp = 0; jp < 32; jp++) {
            float2 v = unpack2(t[jp]);
            hf[2 * jp]     = fmaxf(v.x * sc1[2 * jp]     + of1[2 * jp],     0.f);
            hf[2 * jp + 1] = fmaxf(v.y * sc1[2 * jp + 1] + of1[2 * jp + 1], 0.f);
        }
    }
    // ---- loop 4: r = relu(bn(hf @ Wm2)); part = dot(r, w3) ----
    float part = 0.f;
    {
        u64 q[32];
#pragma unroll
        for (int jp = 0; jp < 32; jp++) q[jp] = 0ull;
#pragma unroll
        for (int k = 0; k < 64; k++) fma_row64(q, W2s + k * 64, dup2(hf[k]));
#pragma unroll
        for (int jp = 0; jp < 32; jp++) {
            float2 v = unpack2(q[jp]);
            float r0 = fmaxf(v.x * sc2[2 * jp]     + of2[2 * jp],     0.f);
            float r1 = fmaxf(v.y * sc2[2 * jp + 1] + of2[2 * jp + 1], 0.f);
            part += r0 * w3s[2 * jp] + r1 * w3s[2 * jp + 1];
        }
    }
    outp[n] = 1.0f / (1.0f + expf(-(part + b3s[0])));
}

// -------------------------------- launcher ----------------------------------
extern "C" void kernel_launch(void* const* d_in, const int* in_sizes, int n_in,
                              void* d_out, int out_size) {
    const float* x   = (const float*)d_in[0];
    const int*   ei  = (const int*)d_in[1];
    const float* Wp1 = (const float*)d_in[2];
    const float* bp1 = (const float*)d_in[3];
    const float* Wn1 = (const float*)d_in[4];
    const float* bn1 = (const float*)d_in[5];
    const float* Wp2 = (const float*)d_in[6];
    const float* bp2 = (const float*)d_in[7];
    const float* Wn2 = (const float*)d_in[8];
    const float* bn2 = (const float*)d_in[9];
    const float* Ww  = (const float*)d_in[10];
    const float* bw  = (const float*)d_in[11];
    const float* Wm1 = (const float*)d_in[12];
    const float* bm1 = (const float*)d_in[13];
    const float* g1  = (const float*)d_in[14];
    const float* be1 = (const float*)d_in[15];
    const float* rm1 = (const float*)d_in[16];
    const float* rv1 = (const float*)d_in[17];
    const float* Wm2 = (const float*)d_in[18];
    const float* bm2 = (const float*)d_in[19];
    const float* g2  = (const float*)d_in[20];
    const float* be2 = (const float*)d_in[21];
    const float* rm2 = (const float*)d_in[22];
    const float* rv2 = (const float*)d_in[23];
    const float* Wm3 = (const float*)d_in[24];
    const float* bm3 = (const float*)d_in[25];

    int  Nn = in_sizes[0] / DD;
    int  E  = in_sizes[1] / 3;

    float* out  = (float*)d_out;
    float* outz = out;
    float* outp = out + (size_t)Nn * DD;

    const int NODE2_SMEM = (96 * 32 * 2 + 64 * 64 * 3 + 32 * 2 + 64 * 6 + 4) * 4;
    cudaFuncSetAttribute(k_node2, cudaFuncAttributeMaxDynamicSharedMemorySize,
                         NODE2_SMEM);

    k_zero<<<2048, 256>>>(Nn);
    k_pack<<<(E + 255) / 256, 256>>>(ei, E);
    k_proj1<<<(Nn + 255) / 256, 256>>>(x, Wp1, Wn1, Nn);

    long t1 = (long)E * 4;
    k_edge1<<<(int)((t1 + 255) / 256), 256>>>(t1);

    k_node1<<<(Nn + 255) / 256, 256>>>(x, Wp1, bp1, Wn1, bn1, Nn);

    long t2 = (long)E * 8;
    k_edge2<<<(int)((t2 + 255) / 256), 256>>>(t2);

    k_node2<<<(Nn + 127) / 128, 128, NODE2_SMEM>>>(
        Wp2, bp2, Wn2, bn2, Ww, bw,
        Wm1, bm1, g1, be1, rm1, rv1,
        Wm2, bm2, g2, be2, rm2, rv2,
        Wm3, bm3, outz, outp, Nn);
}